// round 15
// baseline (speedup 1.0000x reference)
#include <cuda_runtime.h>
#include <math.h>

#define NN 50000
#define NE_MAX 800000
#define TE_MAX (NE_MAX + NN)
#define NG 128
#define SB 49   // scan blocks (49*1024 >= 50000)

// ---------------- scratch (device globals; no allocation) ----------------
__device__ __align__(16) float d_ss1[NN * 4];
__device__ __align__(16) float d_sd1[NN * 4];
__device__ __align__(16) float d_h2[NN * 64];     // h2 = g1@W2 (g1 never materialized)
__device__ __align__(16) float d_gc[NN * 64];     // relu(GCN + bg)
__device__ __align__(16) float d_g2[NN * 64];     // elu(GAT2 + b2)
__device__ __align__(16) float d_y[NN * 56];      // per-node per-head weighted x sums
__device__ __align__(16) float d_den[NN * 4];     // softmax denominators (4 heads)
__device__ __align__(16) float d_xp[NN * 16];     // x padded: [x(14), dinv, 0]
__device__ float d_ss2[NN];
__device__ float d_sd2[NN];
__device__ float d_pooled[NG * 64];   // self-restoring: zeroed by k_head after read
__device__ float d_gcnt[NG];          // self-restoring: zeroed by k_head after read
// CSR by destination. d_off holds EXCLUSIVE-WITHIN-SCAN-BLOCK prefixes;
// consumers add spre[idx>>10] computed from d_bsum in smem.
__device__ int d_cnt_i[NN];           // self-restoring: k_init +1/edge, k_fill -1/edge -> 0
__device__ int d_off[NN + 1];
__device__ int d_csr[TE_MAX];
__device__ int d_bsum[SB];

__device__ __forceinline__ float lrelu(float u) { return u > 0.f ? u : 0.2f * u; }
__device__ __forceinline__ float elu(float u)   { return u > 0.f ? u : expm1f(u); }

// scan d_bsum (SB entries) into spre[SB+1] in smem; call with >=1 warp, then __syncthreads
__device__ __forceinline__ void load_spre(int* spre, int t) {
    if (t == 0) {
        int run = 0;
#pragma unroll
        for (int i = 0; i < SB; i++) { spre[i] = run; run += d_bsum[i]; }
        spre[SB] = run;
    }
}

// ---------------- init+count: degree count; pack x; GAT1 scores via folded A1 ----------------
__global__ void k_init(const float* __restrict__ x, const float* __restrict__ W1,
                       const float* __restrict__ as1, const float* __restrict__ ad1,
                       const int* __restrict__ ei, int E, int te) {
    __shared__ float sAs[56], sAd[56];
    int t = threadIdx.x;
    if (t < 56) {                       // per-block redundant fold: A1 = W1 @ a1 (14x4)
        int k = t >> 2, h = t & 3;
        float ss = 0.f, sd = 0.f;
#pragma unroll 8
        for (int c = 0; c < 64; c++) {
            float w = W1[k * 256 + h * 64 + c];
            ss += w * as1[h * 64 + c];
            sd += w * ad1[h * 64 + c];
        }
        sAs[t] = ss;
        sAd[t] = sd;
    }
    __syncthreads();
    int i  = blockIdx.x * blockDim.x + t;
    int st = gridDim.x * blockDim.x;
    for (int e = i; e < te; e += st) {
        int d = (e < E) ? ei[E + e] : (e - E);
        atomicAdd(&d_cnt_i[d], 1);
    }
    for (int n = i; n < NN; n += st) {
        float xv[14];
#pragma unroll
        for (int k = 0; k < 14; k++) xv[k] = x[n * 14 + k];
        float s4[4] = {}, p4[4] = {};
#pragma unroll
        for (int k = 0; k < 14; k++) {
#pragma unroll
            for (int h = 0; h < 4; h++) {
                s4[h] += xv[k] * sAs[k * 4 + h];
                p4[h] += xv[k] * sAd[k * 4 + h];
            }
        }
        ((float4*)d_ss1)[n] = make_float4(s4[0], s4[1], s4[2], s4[3]);
        ((float4*)d_sd1)[n] = make_float4(p4[0], p4[1], p4[2], p4[3]);
        float4* xr = (float4*)(d_xp + n * 16);
        xr[0] = make_float4(xv[0], xv[1], xv[2], xv[3]);
        xr[1] = make_float4(xv[4], xv[5], xv[6], xv[7]);
        xr[2] = make_float4(xv[8], xv[9], xv[10], xv[11]);
        xr[3] = make_float4(xv[12], xv[13], 0.f, 0.f);   // slot 14 = dinv (set by scan1)
    }
}

// ---------------- scan1: per-block exclusive scan + block sums + dinv ----------------
__global__ void k_scan1() {
    __shared__ int sh[1024];
    int t = threadIdx.x;
    int idx = blockIdx.x * 1024 + t;
    int v = (idx < NN) ? d_cnt_i[idx] : 0;
    sh[t] = v;
    __syncthreads();
    for (int o = 1; o < 1024; o <<= 1) {
        int u = (t >= o) ? sh[t - o] : 0;
        __syncthreads();
        sh[t] += u;
        __syncthreads();
    }
    if (idx < NN) {
        d_off[idx] = sh[t] - v;   // exclusive within block
        d_xp[idx * 16 + 14] = rsqrtf((float)v);
        if (idx == NN - 1) d_off[NN] = sh[t];  // inclusive (exclusive for virtual elem NN)
    }
    if (t == 1023) d_bsum[blockIdx.x] = sh[1023];
}

// fill: final offset = d_off[d] + spre[d>>10]; slot from decrementing cnt_i (ends at 0)
__global__ void k_fill(const int* __restrict__ ei, int E, int te) {
    __shared__ int spre[SB + 1];
    int t = threadIdx.x;
    load_spre(spre, t);
    __syncthreads();
    int e = blockIdx.x * blockDim.x + t;
    if (e >= te) return;
    int s, d;
    if (e < E) { s = ei[e]; d = ei[E + e]; } else { s = d = e - E; }
    int idx = atomicAdd(&d_cnt_i[d], -1) - 1;
    d_csr[d_off[d] + spre[d >> 10] + idx] = s;
}

// ---------------- gather1: FOUR threads per node; fused gc epilogue ----------------
__global__ void k_gather1(const float* __restrict__ Wg, const float* __restrict__ bg) {
    __shared__ float sWg[14][64];
    __shared__ float sbg[64];
    __shared__ int spre[SB + 1];
    int t = threadIdx.x;
    load_spre(spre, t);
    for (int i = t; i < 14 * 64; i += 256) sWg[i >> 6][i & 63] = Wg[i];
    if (t < 64) sbg[t] = bg[t];
    __syncthreads();
    int gid = blockIdx.x * blockDim.x + t;
    int n = gid >> 2, par = gid & 3;
    bool valid = n < NN;
    if (n >= NN) n = NN - 1;           // clamp: keep lanes converged for shuffles
    float4 sdv = ((const float4*)d_sd1)[n];
    int beg = d_off[n] + spre[n >> 10];
    int end = d_off[n + 1] + spre[(n + 1) >> 10];
    float y0[14] = {}, y1[14] = {}, y2[14] = {}, y3[14] = {};
    float z[14] = {};
    float den0 = 0.f, den1 = 0.f, den2 = 0.f, den3 = 0.f;
    for (int i = beg + par; i < end; i += 4) {
        int s = d_csr[i];
        float4 ssv = ((const float4*)d_ss1)[s];
        const float4* xr = (const float4*)(d_xp + s * 16);
        float4 xa = xr[0], xb = xr[1], xc = xr[2], xd = xr[3];
        float dis = xd.z;              // dinv[s] packed at slot 14
        float e0 = __expf(lrelu(ssv.x + sdv.x));
        float e1 = __expf(lrelu(ssv.y + sdv.y));
        float e2 = __expf(lrelu(ssv.z + sdv.z));
        float e3 = __expf(lrelu(ssv.w + sdv.w));
        den0 += e0; den1 += e1; den2 += e2; den3 += e3;
        float xv[14] = {xa.x, xa.y, xa.z, xa.w, xb.x, xb.y, xb.z, xb.w,
                        xc.x, xc.y, xc.z, xc.w, xd.x, xd.y};
#pragma unroll
        for (int k = 0; k < 14; k++) {
            float v = xv[k];
            y0[k] += e0 * v;
            y1[k] += e1 * v;
            y2[k] += e2 * v;
            y3[k] += e3 * v;
            z[k]  += dis * v;
        }
    }
#pragma unroll
    for (int m = 1; m <= 2; m <<= 1) {
#pragma unroll
        for (int k = 0; k < 14; k++) {
            y0[k] += __shfl_xor_sync(0xFFFFFFFFu, y0[k], m);
            y1[k] += __shfl_xor_sync(0xFFFFFFFFu, y1[k], m);
            y2[k] += __shfl_xor_sync(0xFFFFFFFFu, y2[k], m);
            y3[k] += __shfl_xor_sync(0xFFFFFFFFu, y3[k], m);
            z[k]  += __shfl_xor_sync(0xFFFFFFFFu, z[k], m);
        }
        den0 += __shfl_xor_sync(0xFFFFFFFFu, den0, m);
        den1 += __shfl_xor_sync(0xFFFFFFFFu, den1, m);
        den2 += __shfl_xor_sync(0xFFFFFFFFu, den2, m);
        den3 += __shfl_xor_sync(0xFFFFFFFFu, den3, m);
    }
    if (valid) {
        float* yp = d_y + n * 56;
        if (par == 0) {
#pragma unroll
            for (int k = 0; k < 14; k++) { yp[k] = y0[k]; yp[14 + k] = y1[k]; }
            ((float4*)d_den)[n] = make_float4(den0, den1, den2, den3);
        } else if (par == 1) {
#pragma unroll
            for (int k = 0; k < 14; k++) { yp[28 + k] = y2[k]; yp[42 + k] = y3[k]; }
        } else {
            float dvn = d_xp[n * 16 + 14];
            int c0 = (par - 2) * 32;
            float4* gout = (float4*)(d_gc + (long)n * 64 + c0);
#pragma unroll
            for (int c4 = 0; c4 < 8; c4++) {
                float a0 = 0.f, a1 = 0.f, a2 = 0.f, a3 = 0.f;
#pragma unroll
                for (int k = 0; k < 14; k++) {
                    float zv = z[k];
                    const float* wr = &sWg[k][c0 + c4 * 4];
                    a0 += zv * wr[0]; a1 += zv * wr[1]; a2 += zv * wr[2]; a3 += zv * wr[3];
                }
                gout[c4] = make_float4(fmaxf(dvn * a0 + sbg[c0 + c4 * 4 + 0], 0.f),
                                       fmaxf(dvn * a1 + sbg[c0 + c4 * 4 + 1], 0.f),
                                       fmaxf(dvn * a2 + sbg[c0 + c4 * 4 + 2], 0.f),
                                       fmaxf(dvn * a3 + sbg[c0 + c4 * 4 + 3], 0.f));
            }
        }
    }
}

// ---------------- fuse2: h2 = elu((y/den)@W1 + b1) @ W2, g1 never materialized ----------------
__global__ void k_fuse2(const float* __restrict__ W1, const float* __restrict__ b1,
                        const float* __restrict__ W2,
                        const float* __restrict__ as2, const float* __restrict__ ad2) {
    __shared__ float sA[64][68];
    __shared__ float sB[64][68];
    __shared__ float sW1c[14][64];
    __shared__ float sYc[64][16];
    __shared__ float sden[64];
    __shared__ float sb1c[64];
    int t = threadIdx.x;
    int nb = blockIdx.x * 64;
    int tn = t >> 4, tc = t & 15;
    float acc[4][4] = {};
#pragma unroll 1
    for (int kc = 0; kc < 4; kc++) {
#pragma unroll
        for (int j = 0; j < 4; j++) {
            int f4 = t * 4 + j;
            int row = f4 >> 4, col4 = f4 & 15;
            float4 wv = ((const float4*)(W2 + (kc * 64 + row) * 64))[col4];
            ((float4*)&sB[row][0])[col4] = wv;
        }
        for (int i = t; i < 14 * 64; i += 256) {
            int k = i >> 6, c = i & 63;
            sW1c[k][c] = W1[k * 256 + kc * 64 + c];
        }
        for (int i = t; i < 64 * 14; i += 256) {
            int row = i / 14, k = i - row * 14;
            int n = nb + row;
            sYc[row][k] = (n < NN) ? d_y[n * 56 + kc * 14 + k] : 0.f;
        }
        if (t < 64) {
            int n = nb + t;
            sden[t] = (n < NN) ? d_den[n * 4 + kc] : 1.f;
            sb1c[t] = b1[kc * 64 + t];
        }
        __syncthreads();
        {
            float invr[4];
#pragma unroll
            for (int i = 0; i < 4; i++) invr[i] = 1.f / (sden[tn * 4 + i] + 1e-16f);
            float accb[4][4] = {};
#pragma unroll
            for (int k = 0; k < 14; k++) {
                float yv0 = sYc[tn * 4 + 0][k], yv1 = sYc[tn * 4 + 1][k];
                float yv2 = sYc[tn * 4 + 2][k], yv3 = sYc[tn * 4 + 3][k];
                float wv0 = sW1c[k][tc * 4 + 0], wv1 = sW1c[k][tc * 4 + 1];
                float wv2 = sW1c[k][tc * 4 + 2], wv3 = sW1c[k][tc * 4 + 3];
                accb[0][0] += yv0 * wv0; accb[0][1] += yv0 * wv1; accb[0][2] += yv0 * wv2; accb[0][3] += yv0 * wv3;
                accb[1][0] += yv1 * wv0; accb[1][1] += yv1 * wv1; accb[1][2] += yv1 * wv2; accb[1][3] += yv1 * wv3;
                accb[2][0] += yv2 * wv0; accb[2][1] += yv2 * wv1; accb[2][2] += yv2 * wv2; accb[2][3] += yv2 * wv3;
                accb[3][0] += yv3 * wv0; accb[3][1] += yv3 * wv1; accb[3][2] += yv3 * wv2; accb[3][3] += yv3 * wv3;
            }
#pragma unroll
            for (int i = 0; i < 4; i++)
#pragma unroll
                for (int j = 0; j < 4; j++)
                    sA[tn * 4 + i][tc * 4 + j] = elu(accb[i][j] * invr[i] + sb1c[tc * 4 + j]);
        }
        __syncthreads();
#pragma unroll 4
        for (int kk = 0; kk < 64; kk++) {
            float4 bv = ((float4*)&sB[kk][0])[tc];
#pragma unroll
            for (int i = 0; i < 4; i++) {
                float av = sA[tn * 4 + i][kk];
                acc[i][0] += av * bv.x; acc[i][1] += av * bv.y;
                acc[i][2] += av * bv.z; acc[i][3] += av * bv.w;
            }
        }
        __syncthreads();
    }
    float4 av2 = ((const float4*)as2)[tc];
    float4 dv2 = ((const float4*)ad2)[tc];
#pragma unroll
    for (int i = 0; i < 4; i++) {
        int n = nb + tn * 4 + i;
        float ps = acc[i][0] * av2.x + acc[i][1] * av2.y + acc[i][2] * av2.z + acc[i][3] * av2.w;
        float pd = acc[i][0] * dv2.x + acc[i][1] * dv2.y + acc[i][2] * dv2.z + acc[i][3] * dv2.w;
#pragma unroll
        for (int o = 8; o > 0; o >>= 1) {
            ps += __shfl_down_sync(0xFFFFFFFFu, ps, o, 16);
            pd += __shfl_down_sync(0xFFFFFFFFu, pd, o, 16);
        }
        if (n < NN) {
            ((float4*)(d_h2 + (long)n * 64))[tc] =
                make_float4(acc[i][0], acc[i][1], acc[i][2], acc[i][3]);
            if (tc == 0) { d_ss2[n] = ps; d_sd2[n] = pd; }
        }
    }
}

// ---------------- gat2lite: edge gather only -> g2 = elu(softmax-agg(h2) + b2) ----------------
#define G2W 8
__global__ void k_gat2lite(const float* __restrict__ b2) {
    __shared__ int spre[SB + 1];
    int t = threadIdx.x, lane = t & 31, w = t >> 5;
    load_spre(spre, t);
    int c = 2 * lane;
    float b2a = __ldg(b2 + c), b2b = __ldg(b2 + c + 1);
    __syncthreads();
#pragma unroll 1
    for (int q = 0; q < G2W; q++) {
        int n = blockIdx.x * (8 * G2W) + w * G2W + q;
        if (n >= NN) return;
        float sdv = d_sd2[n];
        int beg = d_off[n] + spre[n >> 10];
        int end = d_off[n + 1] + spre[(n + 1) >> 10];
        float a0 = 0.f, a1 = 0.f, den = 0.f;
        int i = beg;
        for (; i + 2 <= end; i += 2) {
            int s0 = d_csr[i], s1 = d_csr[i + 1];
            float l0 = d_ss2[s0], l1 = d_ss2[s1];
            float2 h0 = ((const float2*)(d_h2 + (long)s0 * 64))[lane];
            float2 h1v = ((const float2*)(d_h2 + (long)s1 * 64))[lane];
            float e0 = __expf(lrelu(l0 + sdv));
            float e1 = __expf(lrelu(l1 + sdv));
            den += e0 + e1;
            a0 += h0.x * e0 + h1v.x * e1;
            a1 += h0.y * e0 + h1v.y * e1;
        }
        if (i < end) {
            int s = d_csr[i];
            float e = __expf(lrelu(d_ss2[s] + sdv));
            den += e;
            float2 h = ((const float2*)(d_h2 + (long)s * 64))[lane];
            a0 += h.x * e; a1 += h.y * e;
        }
        float inv = 1.f / (den + 1e-16f);
        ((float2*)(d_g2 + (long)n * 64))[lane] =
            make_float2(elu(a0 * inv + b2a), elu(a1 * inv + b2b));
    }
}

// ---------------- pool: fused = relu([g2|gc]@Wf + bf); segment-reduced pooling + gcnt ----------------
__global__ void k_pool(const float* __restrict__ Wf, const float* __restrict__ bf,
                       const int* __restrict__ batch) {
    __shared__ float sA[64][68];
    __shared__ float sB[64][68];
    __shared__ int sBt[64];
    int t = threadIdx.x;
    int nb = blockIdx.x * 64;
    int tn = t >> 4, tc = t & 15;
    if (t < 64) sBt[t] = (nb + t < NN) ? batch[nb + t] : -1;
    float acc[4][4] = {};
#pragma unroll 1
    for (int kc = 0; kc < 2; kc++) {
        const float* src = kc ? d_gc : d_g2;
#pragma unroll
        for (int j = 0; j < 4; j++) {
            int f4 = t * 4 + j;
            int row = f4 >> 4, col4 = f4 & 15;
            float4 wv = ((const float4*)(Wf + (kc * 64 + row) * 64))[col4];
            ((float4*)&sB[row][0])[col4] = wv;
            int n = nb + row;
            float4 v = (n < NN) ? ((const float4*)(src + (long)n * 64))[col4]
                                : make_float4(0.f, 0.f, 0.f, 0.f);
            ((float4*)&sA[row][0])[col4] = v;
        }
        __syncthreads();
#pragma unroll 4
        for (int kk = 0; kk < 64; kk++) {
            float4 bv = ((float4*)&sB[kk][0])[tc];
#pragma unroll
            for (int i = 0; i < 4; i++) {
                float av = sA[tn * 4 + i][kk];
                acc[i][0] += av * bv.x; acc[i][1] += av * bv.y;
                acc[i][2] += av * bv.z; acc[i][3] += av * bv.w;
            }
        }
        __syncthreads();
    }
    float4 bfv = ((const float4*)bf)[tc];
#pragma unroll
    for (int i = 0; i < 4; i++) {
        int row = tn * 4 + i;
        bool v = (nb + row) < NN;
        sA[row][tc * 4 + 0] = v ? fmaxf(acc[i][0] + bfv.x, 0.f) : 0.f;
        sA[row][tc * 4 + 1] = v ? fmaxf(acc[i][1] + bfv.y, 0.f) : 0.f;
        sA[row][tc * 4 + 2] = v ? fmaxf(acc[i][2] + bfv.z, 0.f) : 0.f;
        sA[row][tc * 4 + 3] = v ? fmaxf(acc[i][3] + bfv.w, 0.f) : 0.f;
    }
    __syncthreads();
    if (t < 64) {
        float run = 0.f;
        int cur = sBt[0];
#pragma unroll 8
        for (int r = 0; r < 64; r++) {
            int b = sBt[r];
            if (b != cur) {
                if (cur >= 0) atomicAdd(d_pooled + cur * 64 + t, run);
                run = 0.f;
                cur = b;
            }
            run += sA[r][t];
        }
        if (cur >= 0) atomicAdd(d_pooled + cur * 64 + t, run);
    } else if (t == 64) {
        int r = 0;
        while (r < 64) {
            int b = sBt[r], r0 = r;
            while (r < 64 && sBt[r] == b) r++;
            if (b >= 0) atomicAdd(&d_gcnt[b], (float)(r - r0));
        }
    }
}

// ---------------- heads: pooled mean -> 2x (relu MLP 64->32->5); self-zero pooled/gcnt ----------------
__global__ void k_head(const float* __restrict__ Wc1, const float* __restrict__ bc1,
                       const float* __restrict__ Wc2, const float* __restrict__ bc2,
                       const float* __restrict__ Wp1, const float* __restrict__ bp1,
                       const float* __restrict__ Wp2, const float* __restrict__ bp2,
                       float* __restrict__ out) {
    int g = blockIdx.x, t = threadIdx.x;
    __shared__ float sp[64], sh[64];
    float cnt = fmaxf(d_gcnt[g], 1.0f);
    sp[t] = d_pooled[g * 64 + t] / cnt;
    d_pooled[g * 64 + t] = 0.f;      // restore for next replay
    if (t == 0) d_gcnt[g] = 0.f;     // restore for next replay
    __syncthreads();
    float hv;
    if (t < 32) {
        hv = bc1[t];
#pragma unroll 8
        for (int k = 0; k < 64; k++) hv += sp[k] * Wc1[k * 32 + t];
    } else {
        int j = t - 32;
        hv = bp1[j];
#pragma unroll 8
        for (int k = 0; k < 64; k++) hv += sp[k] * Wp1[k * 32 + j];
    }
    sh[t] = fmaxf(hv, 0.f);
    __syncthreads();
    if (t < 5) {
        float o = bc2[t];
#pragma unroll
        for (int j = 0; j < 32; j++) o += sh[j] * Wc2[j * 5 + t];
        out[g * 5 + t] = o;
    } else if (t >= 8 && t < 13) {
        int u = t - 8;
        float o = bp2[u];
#pragma unroll
        for (int j = 0; j < 32; j++) o += sh[32 + j] * Wp2[j * 5 + u];
        out[NG * 5 + g * 5 + u] = o;
    }
}

extern "C" void kernel_launch(void* const* d_in, const int* in_sizes, int n_in,
                              void* d_out, int out_size) {
    const float* x     = (const float*)d_in[0];
    const int*   ei    = (const int*)d_in[1];     // int32 (JAX x64 disabled)
    const int*   batch = (const int*)d_in[3];     // int32
    const float* W1  = (const float*)d_in[4];
    const float* as1 = (const float*)d_in[5];
    const float* ad1 = (const float*)d_in[6];
    const float* b1  = (const float*)d_in[7];
    const float* W2  = (const float*)d_in[8];
    const float* as2 = (const float*)d_in[9];
    const float* ad2 = (const float*)d_in[10];
    const float* b2  = (const float*)d_in[11];
    const float* Wg  = (const float*)d_in[12];
    const float* bg  = (const float*)d_in[13];
    const float* Wf  = (const float*)d_in[14];
    const float* bf  = (const float*)d_in[15];
    const float* Wc1 = (const float*)d_in[16];
    const float* bc1 = (const float*)d_in[17];
    const float* Wc2 = (const float*)d_in[18];
    const float* bc2 = (const float*)d_in[19];
    const float* Wp1 = (const float*)d_in[20];
    const float* bp1 = (const float*)d_in[21];
    const float* Wp2 = (const float*)d_in[22];
    const float* bp2 = (const float*)d_in[23];

    int E  = in_sizes[1] / 2;
    int te = E + NN;
    int eb = (te + 255) / 256;

    k_init<<<512, 256>>>(x, W1, as1, ad1, ei, E, te);         // 0
    k_scan1<<<SB, 1024>>>();                                  // 1
    k_fill<<<eb, 256>>>(ei, E, te);                           // 2
    k_gather1<<<(4 * NN + 255) / 256, 256>>>(Wg, bg);         // 3 <- profiled
    k_fuse2<<<(NN + 63) / 64, 256>>>(W1, b1, W2, as2, ad2);   // 4
    k_gat2lite<<<(NN + G2W * 8 - 1) / (G2W * 8), 256>>>(b2);  // 5
    k_pool<<<(NN + 63) / 64, 256>>>(Wf, bf, batch);           // 6
    k_head<<<NG, 64>>>(Wc1, bc1, Wc2, bc2, Wp1, bp1, Wp2, bp2, (float*)d_out); // 7
}

// round 16
// speedup vs baseline: 1.0358x; 1.0358x over previous
#include <cuda_runtime.h>
#include <math.h>

#define NN 50000
#define NE_MAX 800000
#define TE_MAX (NE_MAX + NN)
#define NG 128
#define SB 49   // scan blocks (49*1024 >= 50000)

// ---------------- scratch (device globals; no allocation) ----------------
__device__ __align__(16) float d_ss1[NN * 4];
__device__ __align__(16) float d_sd1[NN * 4];
__device__ __align__(16) float d_h2[NN * 64];     // h2 = g1@W2 (g1 never materialized)
__device__ __align__(16) float d_gc[NN * 64];     // relu(GCN + bg)
__device__ __align__(16) float d_g2[NN * 64];     // elu(GAT2 + b2)
__device__ __align__(16) float d_y[NN * 64];      // per-node per-head weighted x sums [n][h][16]
__device__ __align__(16) float d_den[NN * 4];     // softmax denominators (4 heads)
__device__ __align__(16) float d_xp[NN * 16];     // x padded: [x(14), dinv, 0]
__device__ float d_ss2[NN];
__device__ float d_sd2[NN];
__device__ float d_pooled[NG * 64];   // self-restoring: zeroed by k_head after read
__device__ float d_gcnt[NG];          // self-restoring: zeroed by k_head after read
// CSR by destination. d_off holds EXCLUSIVE-WITHIN-SCAN-BLOCK prefixes;
// consumers add spre[idx>>10] computed from d_bsum in smem.
__device__ int d_cnt_i[NN];           // self-restoring: k_init +1/edge, k_fill -1/edge -> 0
__device__ int d_off[NN + 1];
__device__ int d_csr[TE_MAX];
__device__ int d_bsum[SB];

__device__ __forceinline__ float lrelu(float u) { return u > 0.f ? u : 0.2f * u; }
__device__ __forceinline__ float elu(float u)   { return u > 0.f ? u : expm1f(u); }

// scan d_bsum (SB entries) into spre[SB+1] in smem; call with >=1 warp, then __syncthreads
__device__ __forceinline__ void load_spre(int* spre, int t) {
    if (t == 0) {
        int run = 0;
#pragma unroll
        for (int i = 0; i < SB; i++) { spre[i] = run; run += d_bsum[i]; }
        spre[SB] = run;
    }
}

// ---------------- init+count: degree count; pack x; GAT1 scores via folded A1 ----------------
__global__ void k_init(const float* __restrict__ x, const float* __restrict__ W1,
                       const float* __restrict__ as1, const float* __restrict__ ad1,
                       const int* __restrict__ ei, int E, int te) {
    __shared__ float sAs[56], sAd[56];
    int t = threadIdx.x;
    if (t < 56) {                       // per-block redundant fold: A1 = W1 @ a1 (14x4)
        int k = t >> 2, h = t & 3;
        float ss = 0.f, sd = 0.f;
#pragma unroll 8
        for (int c = 0; c < 64; c++) {
            float w = W1[k * 256 + h * 64 + c];
            ss += w * as1[h * 64 + c];
            sd += w * ad1[h * 64 + c];
        }
        sAs[t] = ss;
        sAd[t] = sd;
    }
    __syncthreads();
    int i  = blockIdx.x * blockDim.x + t;
    int st = gridDim.x * blockDim.x;
    for (int e = i; e < te; e += st) {
        int d = (e < E) ? ei[E + e] : (e - E);
        atomicAdd(&d_cnt_i[d], 1);
    }
    for (int n = i; n < NN; n += st) {
        float xv[14];
#pragma unroll
        for (int k = 0; k < 14; k++) xv[k] = x[n * 14 + k];
        float s4[4] = {}, p4[4] = {};
#pragma unroll
        for (int k = 0; k < 14; k++) {
#pragma unroll
            for (int h = 0; h < 4; h++) {
                s4[h] += xv[k] * sAs[k * 4 + h];
                p4[h] += xv[k] * sAd[k * 4 + h];
            }
        }
        ((float4*)d_ss1)[n] = make_float4(s4[0], s4[1], s4[2], s4[3]);
        ((float4*)d_sd1)[n] = make_float4(p4[0], p4[1], p4[2], p4[3]);
        float4* xr = (float4*)(d_xp + n * 16);
        xr[0] = make_float4(xv[0], xv[1], xv[2], xv[3]);
        xr[1] = make_float4(xv[4], xv[5], xv[6], xv[7]);
        xr[2] = make_float4(xv[8], xv[9], xv[10], xv[11]);
        xr[3] = make_float4(xv[12], xv[13], 0.f, 0.f);   // slot 14 = dinv (set by scan1)
    }
}

// ---------------- scan1: per-block exclusive scan + block sums + dinv ----------------
__global__ void k_scan1() {
    __shared__ int sh[1024];
    int t = threadIdx.x;
    int idx = blockIdx.x * 1024 + t;
    int v = (idx < NN) ? d_cnt_i[idx] : 0;
    sh[t] = v;
    __syncthreads();
    for (int o = 1; o < 1024; o <<= 1) {
        int u = (t >= o) ? sh[t - o] : 0;
        __syncthreads();
        sh[t] += u;
        __syncthreads();
    }
    if (idx < NN) {
        d_off[idx] = sh[t] - v;   // exclusive within block
        d_xp[idx * 16 + 14] = rsqrtf((float)v);
        if (idx == NN - 1) d_off[NN] = sh[t];
    }
    if (t == 1023) d_bsum[blockIdx.x] = sh[1023];
}

// fill: final offset = d_off[d] + spre[d>>10]; slot from decrementing cnt_i (ends at 0)
__global__ void k_fill(const int* __restrict__ ei, int E, int te) {
    __shared__ int spre[SB + 1];
    int t = threadIdx.x;
    load_spre(spre, t);
    __syncthreads();
    int e = blockIdx.x * blockDim.x + t;
    if (e >= te) return;
    int s, d;
    if (e < E) { s = ei[e]; d = ei[E + e]; } else { s = d = e - E; }
    int idx = atomicAdd(&d_cnt_i[d], -1) - 1;
    d_csr[d_off[d] + spre[d >> 10] + idx] = s;
}

// ---------------- gather1: quad-cooperative (4 lanes share each edge) ----------------
// lane p of a node-quad: loads x-quarter p + head-p score; e exchanged via quad shuffles.
// Accumulates all 4 heads x own quarter (16+4 regs). Epilogue: y + den + gc.
__global__ void __launch_bounds__(128) k_gather1(const float* __restrict__ Wg,
                                                 const float* __restrict__ bg) {
    __shared__ float sWg[14][64];
    __shared__ float sbg[64];
    __shared__ int spre[SB + 1];
    int t = threadIdx.x;
    load_spre(spre, t);
    for (int i = t; i < 14 * 64; i += 128) sWg[i >> 6][i & 63] = Wg[i];
    if (t < 64) sbg[t] = bg[t];
    __syncthreads();
    int gid = blockIdx.x * 128 + t;
    int n = gid >> 2, p = gid & 3;
    bool valid = n < NN;
    if (n >= NN) n = NN - 1;           // clamp: keep quad converged
    int lane = t & 31;
    unsigned qmask = 0xFu << (lane & ~3);
    float sdp = d_sd1[n * 4 + p];
    int beg = d_off[n] + spre[n >> 10];
    int end = d_off[n + 1] + spre[(n + 1) >> 10];
    float4 y0 = make_float4(0.f, 0.f, 0.f, 0.f);   // head p      (own quarter)
    float4 y1 = make_float4(0.f, 0.f, 0.f, 0.f);   // head p^1
    float4 y2 = make_float4(0.f, 0.f, 0.f, 0.f);   // head p^2
    float4 y3 = make_float4(0.f, 0.f, 0.f, 0.f);   // head p^3
    float4 zq = make_float4(0.f, 0.f, 0.f, 0.f);
    float den = 0.f;
    for (int i = beg; i < end; i++) {
        int s = d_csr[i];
        float ssp = d_ss1[s * 4 + p];
        float4 xq = ((const float4*)(d_xp + (long)s * 16))[p];
        float ep = __expf(lrelu(ssp + sdp));
        den += ep;
        float e1 = __shfl_xor_sync(qmask, ep, 1);
        float e2 = __shfl_xor_sync(qmask, ep, 2);
        float e3 = __shfl_xor_sync(qmask, e1, 2);
        float dis = __shfl_sync(qmask, xq.z, lane | 3);   // dinv[s] from lane 3's quarter
        y0.x += ep * xq.x; y0.y += ep * xq.y; y0.z += ep * xq.z; y0.w += ep * xq.w;
        y1.x += e1 * xq.x; y1.y += e1 * xq.y; y1.z += e1 * xq.z; y1.w += e1 * xq.w;
        y2.x += e2 * xq.x; y2.y += e2 * xq.y; y2.z += e2 * xq.z; y2.w += e2 * xq.w;
        y3.x += e3 * xq.x; y3.y += e3 * xq.y; y3.z += e3 * xq.z; y3.w += e3 * xq.w;
        zq.x += dis * xq.x; zq.y += dis * xq.y; zq.z += dis * xq.z; zq.w += dis * xq.w;
    }
    // gather full z (14 valid) before any lane can exit
    float zf[16];
#pragma unroll
    for (int q = 0; q < 4; q++) {
        int src = (lane & ~3) | q;
        zf[q * 4 + 0] = __shfl_sync(qmask, zq.x, src);
        zf[q * 4 + 1] = __shfl_sync(qmask, zq.y, src);
        zf[q * 4 + 2] = __shfl_sync(qmask, zq.z, src);
        zf[q * 4 + 3] = __shfl_sync(qmask, zq.w, src);
    }
    if (!valid) return;
    d_den[n * 4 + p] = den;
    // y: head h's quarter p lives in register y[p^h]
#pragma unroll
    for (int h = 0; h < 4; h++) {
        int j = h ^ p;
        float4 v = (j == 0) ? y0 : (j == 1) ? y1 : (j == 2) ? y2 : y3;
        *(float4*)(d_y + (long)n * 64 + h * 16 + p * 4) = v;
    }
    // gc: lane p computes 16 columns [16p, 16p+16)
    float dvn = d_xp[n * 16 + 14];
    int c0 = p * 16;
    float4* gout = (float4*)(d_gc + (long)n * 64 + c0);
#pragma unroll
    for (int c4 = 0; c4 < 4; c4++) {
        float a0 = 0.f, a1 = 0.f, a2 = 0.f, a3 = 0.f;
#pragma unroll
        for (int k = 0; k < 14; k++) {
            float zv = zf[k];
            const float* wr = &sWg[k][c0 + c4 * 4];
            a0 += zv * wr[0]; a1 += zv * wr[1]; a2 += zv * wr[2]; a3 += zv * wr[3];
        }
        gout[c4] = make_float4(fmaxf(dvn * a0 + sbg[c0 + c4 * 4 + 0], 0.f),
                               fmaxf(dvn * a1 + sbg[c0 + c4 * 4 + 1], 0.f),
                               fmaxf(dvn * a2 + sbg[c0 + c4 * 4 + 2], 0.f),
                               fmaxf(dvn * a3 + sbg[c0 + c4 * 4 + 3], 0.f));
    }
}

// ---------------- fuse2: h2 = elu((y/den)@W1 + b1) @ W2, g1 never materialized ----------------
__global__ void k_fuse2(const float* __restrict__ W1, const float* __restrict__ b1,
                        const float* __restrict__ W2,
                        const float* __restrict__ as2, const float* __restrict__ ad2) {
    __shared__ float sA[64][68];
    __shared__ float sB[64][68];
    __shared__ float sW1c[14][64];
    __shared__ float sYc[64][16];
    __shared__ float sden[64];
    __shared__ float sb1c[64];
    int t = threadIdx.x;
    int nb = blockIdx.x * 64;
    int tn = t >> 4, tc = t & 15;
    float acc[4][4] = {};
#pragma unroll 1
    for (int kc = 0; kc < 4; kc++) {
#pragma unroll
        for (int j = 0; j < 4; j++) {
            int f4 = t * 4 + j;
            int row = f4 >> 4, col4 = f4 & 15;
            float4 wv = ((const float4*)(W2 + (kc * 64 + row) * 64))[col4];
            ((float4*)&sB[row][0])[col4] = wv;
        }
        for (int i = t; i < 14 * 64; i += 256) {
            int k = i >> 6, c = i & 63;
            sW1c[k][c] = W1[k * 256 + kc * 64 + c];
        }
        // y rows are [n][h][16] now: 16-float chunks, float4 loads
        for (int i = t; i < 64 * 4; i += 256) {
            int row = i >> 2, q = i & 3;
            int n = nb + row;
            float4 v = (n < NN) ? *(const float4*)(d_y + (long)n * 64 + kc * 16 + q * 4)
                                : make_float4(0.f, 0.f, 0.f, 0.f);
            ((float4*)&sYc[row][0])[q] = v;
        }
        if (t < 64) {
            int n = nb + t;
            sden[t] = (n < NN) ? d_den[n * 4 + kc] : 1.f;
            sb1c[t] = b1[kc * 64 + t];
        }
        __syncthreads();
        {
            float invr[4];
#pragma unroll
            for (int i = 0; i < 4; i++) invr[i] = 1.f / (sden[tn * 4 + i] + 1e-16f);
            float accb[4][4] = {};
#pragma unroll
            for (int k = 0; k < 14; k++) {
                float yv0 = sYc[tn * 4 + 0][k], yv1 = sYc[tn * 4 + 1][k];
                float yv2 = sYc[tn * 4 + 2][k], yv3 = sYc[tn * 4 + 3][k];
                float wv0 = sW1c[k][tc * 4 + 0], wv1 = sW1c[k][tc * 4 + 1];
                float wv2 = sW1c[k][tc * 4 + 2], wv3 = sW1c[k][tc * 4 + 3];
                accb[0][0] += yv0 * wv0; accb[0][1] += yv0 * wv1; accb[0][2] += yv0 * wv2; accb[0][3] += yv0 * wv3;
                accb[1][0] += yv1 * wv0; accb[1][1] += yv1 * wv1; accb[1][2] += yv1 * wv2; accb[1][3] += yv1 * wv3;
                accb[2][0] += yv2 * wv0; accb[2][1] += yv2 * wv1; accb[2][2] += yv2 * wv2; accb[2][3] += yv2 * wv3;
                accb[3][0] += yv3 * wv0; accb[3][1] += yv3 * wv1; accb[3][2] += yv3 * wv2; accb[3][3] += yv3 * wv3;
            }
#pragma unroll
            for (int i = 0; i < 4; i++)
#pragma unroll
                for (int j = 0; j < 4; j++)
                    sA[tn * 4 + i][tc * 4 + j] = elu(accb[i][j] * invr[i] + sb1c[tc * 4 + j]);
        }
        __syncthreads();
#pragma unroll 4
        for (int kk = 0; kk < 64; kk++) {
            float4 bv = ((float4*)&sB[kk][0])[tc];
#pragma unroll
            for (int i = 0; i < 4; i++) {
                float av = sA[tn * 4 + i][kk];
                acc[i][0] += av * bv.x; acc[i][1] += av * bv.y;
                acc[i][2] += av * bv.z; acc[i][3] += av * bv.w;
            }
        }
        __syncthreads();
    }
    float4 av2 = ((const float4*)as2)[tc];
    float4 dv2 = ((const float4*)ad2)[tc];
#pragma unroll
    for (int i = 0; i < 4; i++) {
        int n = nb + tn * 4 + i;
        float ps = acc[i][0] * av2.x + acc[i][1] * av2.y + acc[i][2] * av2.z + acc[i][3] * av2.w;
        float pd = acc[i][0] * dv2.x + acc[i][1] * dv2.y + acc[i][2] * dv2.z + acc[i][3] * dv2.w;
#pragma unroll
        for (int o = 8; o > 0; o >>= 1) {
            ps += __shfl_down_sync(0xFFFFFFFFu, ps, o, 16);
            pd += __shfl_down_sync(0xFFFFFFFFu, pd, o, 16);
        }
        if (n < NN) {
            ((float4*)(d_h2 + (long)n * 64))[tc] =
                make_float4(acc[i][0], acc[i][1], acc[i][2], acc[i][3]);
            if (tc == 0) { d_ss2[n] = ps; d_sd2[n] = pd; }
        }
    }
}

// ---------------- gat2lite: edge gather only -> g2 = elu(softmax-agg(h2) + b2) ----------------
#define G2W 8
__global__ void k_gat2lite(const float* __restrict__ b2) {
    __shared__ int spre[SB + 1];
    int t = threadIdx.x, lane = t & 31, w = t >> 5;
    load_spre(spre, t);
    int c = 2 * lane;
    float b2a = __ldg(b2 + c), b2b = __ldg(b2 + c + 1);
    __syncthreads();
#pragma unroll 1
    for (int q = 0; q < G2W; q++) {
        int n = blockIdx.x * (8 * G2W) + w * G2W + q;
        if (n >= NN) return;
        float sdv = d_sd2[n];
        int beg = d_off[n] + spre[n >> 10];
        int end = d_off[n + 1] + spre[(n + 1) >> 10];
        float a0 = 0.f, a1 = 0.f, den = 0.f;
        int i = beg;
        for (; i + 2 <= end; i += 2) {
            int s0 = d_csr[i], s1 = d_csr[i + 1];
            float l0 = d_ss2[s0], l1 = d_ss2[s1];
            float2 h0 = ((const float2*)(d_h2 + (long)s0 * 64))[lane];
            float2 h1v = ((const float2*)(d_h2 + (long)s1 * 64))[lane];
            float e0 = __expf(lrelu(l0 + sdv));
            float e1 = __expf(lrelu(l1 + sdv));
            den += e0 + e1;
            a0 += h0.x * e0 + h1v.x * e1;
            a1 += h0.y * e0 + h1v.y * e1;
        }
        if (i < end) {
            int s = d_csr[i];
            float e = __expf(lrelu(d_ss2[s] + sdv));
            den += e;
            float2 h = ((const float2*)(d_h2 + (long)s * 64))[lane];
            a0 += h.x * e; a1 += h.y * e;
        }
        float inv = 1.f / (den + 1e-16f);
        ((float2*)(d_g2 + (long)n * 64))[lane] =
            make_float2(elu(a0 * inv + b2a), elu(a1 * inv + b2b));
    }
}

// ---------------- pool: fused = relu([g2|gc]@Wf + bf); segment-reduced pooling + gcnt ----------------
__global__ void k_pool(const float* __restrict__ Wf, const float* __restrict__ bf,
                       const int* __restrict__ batch) {
    __shared__ float sA[64][68];
    __shared__ float sB[64][68];
    __shared__ int sBt[64];
    int t = threadIdx.x;
    int nb = blockIdx.x * 64;
    int tn = t >> 4, tc = t & 15;
    if (t < 64) sBt[t] = (nb + t < NN) ? batch[nb + t] : -1;
    float acc[4][4] = {};
#pragma unroll 1
    for (int kc = 0; kc < 2; kc++) {
        const float* src = kc ? d_gc : d_g2;
#pragma unroll
        for (int j = 0; j < 4; j++) {
            int f4 = t * 4 + j;
            int row = f4 >> 4, col4 = f4 & 15;
            float4 wv = ((const float4*)(Wf + (kc * 64 + row) * 64))[col4];
            ((float4*)&sB[row][0])[col4] = wv;
            int n = nb + row;
            float4 v = (n < NN) ? ((const float4*)(src + (long)n * 64))[col4]
                                : make_float4(0.f, 0.f, 0.f, 0.f);
            ((float4*)&sA[row][0])[col4] = v;
        }
        __syncthreads();
#pragma unroll 4
        for (int kk = 0; kk < 64; kk++) {
            float4 bv = ((float4*)&sB[kk][0])[tc];
#pragma unroll
            for (int i = 0; i < 4; i++) {
                float av = sA[tn * 4 + i][kk];
                acc[i][0] += av * bv.x; acc[i][1] += av * bv.y;
                acc[i][2] += av * bv.z; acc[i][3] += av * bv.w;
            }
        }
        __syncthreads();
    }
    float4 bfv = ((const float4*)bf)[tc];
#pragma unroll
    for (int i = 0; i < 4; i++) {
        int row = tn * 4 + i;
        bool v = (nb + row) < NN;
        sA[row][tc * 4 + 0] = v ? fmaxf(acc[i][0] + bfv.x, 0.f) : 0.f;
        sA[row][tc * 4 + 1] = v ? fmaxf(acc[i][1] + bfv.y, 0.f) : 0.f;
        sA[row][tc * 4 + 2] = v ? fmaxf(acc[i][2] + bfv.z, 0.f) : 0.f;
        sA[row][tc * 4 + 3] = v ? fmaxf(acc[i][3] + bfv.w, 0.f) : 0.f;
    }
    __syncthreads();
    if (t < 64) {
        float run = 0.f;
        int cur = sBt[0];
#pragma unroll 8
        for (int r = 0; r < 64; r++) {
            int b = sBt[r];
            if (b != cur) {
                if (cur >= 0) atomicAdd(d_pooled + cur * 64 + t, run);
                run = 0.f;
                cur = b;
            }
            run += sA[r][t];
        }
        if (cur >= 0) atomicAdd(d_pooled + cur * 64 + t, run);
    } else if (t == 64) {
        int r = 0;
        while (r < 64) {
            int b = sBt[r], r0 = r;
            while (r < 64 && sBt[r] == b) r++;
            if (b >= 0) atomicAdd(&d_gcnt[b], (float)(r - r0));
        }
    }
}

// ---------------- heads: pooled mean -> 2x (relu MLP 64->32->5); self-zero pooled/gcnt ----------------
__global__ void k_head(const float* __restrict__ Wc1, const float* __restrict__ bc1,
                       const float* __restrict__ Wc2, const float* __restrict__ bc2,
                       const float* __restrict__ Wp1, const float* __restrict__ bp1,
                       const float* __restrict__ Wp2, const float* __restrict__ bp2,
                       float* __restrict__ out) {
    int g = blockIdx.x, t = threadIdx.x;
    __shared__ float sp[64], sh[64];
    float cnt = fmaxf(d_gcnt[g], 1.0f);
    sp[t] = d_pooled[g * 64 + t] / cnt;
    d_pooled[g * 64 + t] = 0.f;      // restore for next replay
    if (t == 0) d_gcnt[g] = 0.f;     // restore for next replay
    __syncthreads();
    float hv;
    if (t < 32) {
        hv = bc1[t];
#pragma unroll 8
        for (int k = 0; k < 64; k++) hv += sp[k] * Wc1[k * 32 + t];
    } else {
        int j = t - 32;
        hv = bp1[j];
#pragma unroll 8
        for (int k = 0; k < 64; k++) hv += sp[k] * Wp1[k * 32 + j];
    }
    sh[t] = fmaxf(hv, 0.f);
    __syncthreads();
    if (t < 5) {
        float o = bc2[t];
#pragma unroll
        for (int j = 0; j < 32; j++) o += sh[j] * Wc2[j * 5 + t];
        out[g * 5 + t] = o;
    } else if (t >= 8 && t < 13) {
        int u = t - 8;
        float o = bp2[u];
#pragma unroll
        for (int j = 0; j < 32; j++) o += sh[32 + j] * Wp2[j * 5 + u];
        out[NG * 5 + g * 5 + u] = o;
    }
}

extern "C" void kernel_launch(void* const* d_in, const int* in_sizes, int n_in,
                              void* d_out, int out_size) {
    const float* x     = (const float*)d_in[0];
    const int*   ei    = (const int*)d_in[1];     // int32 (JAX x64 disabled)
    const int*   batch = (const int*)d_in[3];     // int32
    const float* W1  = (const float*)d_in[4];
    const float* as1 = (const float*)d_in[5];
    const float* ad1 = (const float*)d_in[6];
    const float* b1  = (const float*)d_in[7];
    const float* W2  = (const float*)d_in[8];
    const float* as2 = (const float*)d_in[9];
    const float* ad2 = (const float*)d_in[10];
    const float* b2  = (const float*)d_in[11];
    const float* Wg  = (const float*)d_in[12];
    const float* bg  = (const float*)d_in[13];
    const float* Wf  = (const float*)d_in[14];
    const float* bf  = (const float*)d_in[15];
    const float* Wc1 = (const float*)d_in[16];
    const float* bc1 = (const float*)d_in[17];
    const float* Wc2 = (const float*)d_in[18];
    const float* bc2 = (const float*)d_in[19];
    const float* Wp1 = (const float*)d_in[20];
    const float* bp1 = (const float*)d_in[21];
    const float* Wp2 = (const float*)d_in[22];
    const float* bp2 = (const float*)d_in[23];

    int E  = in_sizes[1] / 2;
    int te = E + NN;
    int eb = (te + 255) / 256;

    k_init<<<512, 256>>>(x, W1, as1, ad1, ei, E, te);         // 0
    k_scan1<<<SB, 1024>>>();                                  // 1
    k_fill<<<eb, 256>>>(ei, E, te);                           // 2
    k_gather1<<<(4 * NN + 127) / 128, 128>>>(Wg, bg);         // 3 <- profiled
    k_fuse2<<<(NN + 63) / 64, 256>>>(W1, b1, W2, as2, ad2);   // 4
    k_gat2lite<<<(NN + G2W * 8 - 1) / (G2W * 8), 256>>>(b2);  // 5
    k_pool<<<(NN + 63) / 64, 256>>>(Wf, bf, batch);           // 6
    k_head<<<NG, 64>>>(Wc1, bc1, Wc2, bc2, Wp1, bp1, Wp2, bp2, (float*)d_out); // 7
}

// round 17
// speedup vs baseline: 1.0783x; 1.0410x over previous
#include <cuda_runtime.h>
#include <math.h>

#define NN 50000
#define NE_MAX 800000
#define TE_MAX (NE_MAX + NN)
#define NG 128
#define SB 49   // scan blocks (49*1024 >= 50000)

// ---------------- scratch (device globals; no allocation) ----------------
__device__ __align__(16) float d_ss1[NN * 4];
__device__ __align__(16) float d_sd1[NN * 4];
__device__ __align__(16) float d_h2[NN * 64];     // h2 = g1@W2 (g1 never materialized)
__device__ __align__(16) float d_gc[NN * 64];     // relu(GCN + bg)
__device__ __align__(16) float d_g2[NN * 64];     // elu(GAT2 + b2)
__device__ __align__(16) float d_y[NN * 64];      // per-node per-head weighted x sums [n][h][16]
__device__ __align__(16) float d_den[NN * 4];     // softmax denominators (4 heads)
__device__ __align__(16) float d_xp[NN * 16];     // x padded: [x(14), dinv, 0]
__device__ float d_ss2[NN];
__device__ float d_sd2[NN];
__device__ float d_pooled[NG * 64];   // self-restoring: zeroed by k_head after read
__device__ float d_gcnt[NG];          // self-restoring: zeroed by k_head after read
// CSR by destination. d_off holds EXCLUSIVE-WITHIN-SCAN-BLOCK prefixes;
// consumers add spre[idx>>10] computed from d_bsum in smem.
__device__ int d_cnt_i[NN];           // self-restoring: k_init +1/edge, k_fill -1/edge -> 0
__device__ int d_off[NN + 1];
__device__ int d_csr[TE_MAX];
__device__ int d_bsum[SB];

__device__ __forceinline__ float lrelu(float u) { return u > 0.f ? u : 0.2f * u; }
__device__ __forceinline__ float elu(float u)   { return u > 0.f ? u : expm1f(u); }

// scan d_bsum (SB entries) into spre[SB+1] in smem; call with >=1 warp, then __syncthreads
__device__ __forceinline__ void load_spre(int* spre, int t) {
    if (t == 0) {
        int run = 0;
#pragma unroll
        for (int i = 0; i < SB; i++) { spre[i] = run; run += d_bsum[i]; }
        spre[SB] = run;
    }
}

// ---------------- init+count: degree count; pack x; GAT1 scores via folded A1 ----------------
__global__ void k_init(const float* __restrict__ x, const float* __restrict__ W1,
                       const float* __restrict__ as1, const float* __restrict__ ad1,
                       const int* __restrict__ ei, int E, int te) {
    __shared__ float sAs[56], sAd[56];
    int t = threadIdx.x;
    if (t < 56) {                       // per-block redundant fold: A1 = W1 @ a1 (14x4)
        int k = t >> 2, h = t & 3;
        float ss = 0.f, sd = 0.f;
#pragma unroll 8
        for (int c = 0; c < 64; c++) {
            float w = W1[k * 256 + h * 64 + c];
            ss += w * as1[h * 64 + c];
            sd += w * ad1[h * 64 + c];
        }
        sAs[t] = ss;
        sAd[t] = sd;
    }
    __syncthreads();
    int i  = blockIdx.x * blockDim.x + t;
    int st = gridDim.x * blockDim.x;
    for (int e = i; e < te; e += st) {
        int d = (e < E) ? ei[E + e] : (e - E);
        atomicAdd(&d_cnt_i[d], 1);
    }
    for (int n = i; n < NN; n += st) {
        float xv[14];
#pragma unroll
        for (int k = 0; k < 14; k++) xv[k] = x[n * 14 + k];
        float s4[4] = {}, p4[4] = {};
#pragma unroll
        for (int k = 0; k < 14; k++) {
#pragma unroll
            for (int h = 0; h < 4; h++) {
                s4[h] += xv[k] * sAs[k * 4 + h];
                p4[h] += xv[k] * sAd[k * 4 + h];
            }
        }
        ((float4*)d_ss1)[n] = make_float4(s4[0], s4[1], s4[2], s4[3]);
        ((float4*)d_sd1)[n] = make_float4(p4[0], p4[1], p4[2], p4[3]);
        float4* xr = (float4*)(d_xp + n * 16);
        xr[0] = make_float4(xv[0], xv[1], xv[2], xv[3]);
        xr[1] = make_float4(xv[4], xv[5], xv[6], xv[7]);
        xr[2] = make_float4(xv[8], xv[9], xv[10], xv[11]);
        xr[3] = make_float4(xv[12], xv[13], 0.f, 0.f);   // slot 14 = dinv (set by scan1)
    }
}

// ---------------- scan1: per-block exclusive scan + block sums + dinv ----------------
__global__ void k_scan1() {
    __shared__ int sh[1024];
    int t = threadIdx.x;
    int idx = blockIdx.x * 1024 + t;
    int v = (idx < NN) ? d_cnt_i[idx] : 0;
    sh[t] = v;
    __syncthreads();
    for (int o = 1; o < 1024; o <<= 1) {
        int u = (t >= o) ? sh[t - o] : 0;
        __syncthreads();
        sh[t] += u;
        __syncthreads();
    }
    if (idx < NN) {
        d_off[idx] = sh[t] - v;   // exclusive within block
        d_xp[idx * 16 + 14] = rsqrtf((float)v);
        if (idx == NN - 1) d_off[NN] = sh[t];
    }
    if (t == 1023) d_bsum[blockIdx.x] = sh[1023];
}

// fill: final offset = d_off[d] + spre[d>>10]; slot from decrementing cnt_i (ends at 0)
__global__ void k_fill(const int* __restrict__ ei, int E, int te) {
    __shared__ int spre[SB + 1];
    int t = threadIdx.x;
    load_spre(spre, t);
    __syncthreads();
    int e = blockIdx.x * blockDim.x + t;
    if (e >= te) return;
    int s, d;
    if (e < E) { s = ei[e]; d = ei[E + e]; } else { s = d = e - E; }
    int idx = atomicAdd(&d_cnt_i[d], -1) - 1;
    d_csr[d_off[d] + spre[d >> 10] + idx] = s;
}

// ---------------- gather1: quad-cooperative, 2-edge unrolled ----------------
// lane p of a node-quad: loads x-quarter p + head-p score; e exchanged via quad shuffles.
__global__ void __launch_bounds__(128) k_gather1(const float* __restrict__ Wg,
                                                 const float* __restrict__ bg) {
    __shared__ float sWg[14][64];
    __shared__ float sbg[64];
    __shared__ int spre[SB + 1];
    int t = threadIdx.x;
    load_spre(spre, t);
    for (int i = t; i < 14 * 64; i += 128) sWg[i >> 6][i & 63] = Wg[i];
    if (t < 64) sbg[t] = bg[t];
    __syncthreads();
    int gid = blockIdx.x * 128 + t;
    int n = gid >> 2, p = gid & 3;
    bool valid = n < NN;
    if (n >= NN) n = NN - 1;           // clamp: keep quad converged
    int lane = t & 31;
    unsigned qmask = 0xFu << (lane & ~3);
    float sdp = d_sd1[n * 4 + p];
    int beg = d_off[n] + spre[n >> 10];
    int end = d_off[n + 1] + spre[(n + 1) >> 10];
    float4 y0 = make_float4(0.f, 0.f, 0.f, 0.f);   // head p      (own quarter)
    float4 y1 = make_float4(0.f, 0.f, 0.f, 0.f);   // head p^1
    float4 y2 = make_float4(0.f, 0.f, 0.f, 0.f);   // head p^2
    float4 y3 = make_float4(0.f, 0.f, 0.f, 0.f);   // head p^3
    float4 zq = make_float4(0.f, 0.f, 0.f, 0.f);
    float den = 0.f;
    int i = beg;
    for (; i + 2 <= end; i += 2) {
        int s0 = d_csr[i], s1 = d_csr[i + 1];
        float ssp0 = d_ss1[s0 * 4 + p];
        float ssp1 = d_ss1[s1 * 4 + p];
        float4 xq0 = ((const float4*)(d_xp + (long)s0 * 16))[p];
        float4 xq1 = ((const float4*)(d_xp + (long)s1 * 16))[p];
        float ea = __expf(lrelu(ssp0 + sdp));
        float eb = __expf(lrelu(ssp1 + sdp));
        den += ea + eb;
        float ea1 = __shfl_xor_sync(qmask, ea, 1);
        float ea2 = __shfl_xor_sync(qmask, ea, 2);
        float ea3 = __shfl_xor_sync(qmask, ea1, 2);
        float eb1 = __shfl_xor_sync(qmask, eb, 1);
        float eb2 = __shfl_xor_sync(qmask, eb, 2);
        float eb3 = __shfl_xor_sync(qmask, eb1, 2);
        float disa = __shfl_sync(qmask, xq0.z, lane | 3);
        float disb = __shfl_sync(qmask, xq1.z, lane | 3);
        y0.x += ea * xq0.x + eb * xq1.x; y0.y += ea * xq0.y + eb * xq1.y;
        y0.z += ea * xq0.z + eb * xq1.z; y0.w += ea * xq0.w + eb * xq1.w;
        y1.x += ea1 * xq0.x + eb1 * xq1.x; y1.y += ea1 * xq0.y + eb1 * xq1.y;
        y1.z += ea1 * xq0.z + eb1 * xq1.z; y1.w += ea1 * xq0.w + eb1 * xq1.w;
        y2.x += ea2 * xq0.x + eb2 * xq1.x; y2.y += ea2 * xq0.y + eb2 * xq1.y;
        y2.z += ea2 * xq0.z + eb2 * xq1.z; y2.w += ea2 * xq0.w + eb2 * xq1.w;
        y3.x += ea3 * xq0.x + eb3 * xq1.x; y3.y += ea3 * xq0.y + eb3 * xq1.y;
        y3.z += ea3 * xq0.z + eb3 * xq1.z; y3.w += ea3 * xq0.w + eb3 * xq1.w;
        zq.x += disa * xq0.x + disb * xq1.x; zq.y += disa * xq0.y + disb * xq1.y;
        zq.z += disa * xq0.z + disb * xq1.z; zq.w += disa * xq0.w + disb * xq1.w;
    }
    if (i < end) {
        int s = d_csr[i];
        float ssp = d_ss1[s * 4 + p];
        float4 xq = ((const float4*)(d_xp + (long)s * 16))[p];
        float ep = __expf(lrelu(ssp + sdp));
        den += ep;
        float e1 = __shfl_xor_sync(qmask, ep, 1);
        float e2 = __shfl_xor_sync(qmask, ep, 2);
        float e3 = __shfl_xor_sync(qmask, e1, 2);
        float dis = __shfl_sync(qmask, xq.z, lane | 3);
        y0.x += ep * xq.x; y0.y += ep * xq.y; y0.z += ep * xq.z; y0.w += ep * xq.w;
        y1.x += e1 * xq.x; y1.y += e1 * xq.y; y1.z += e1 * xq.z; y1.w += e1 * xq.w;
        y2.x += e2 * xq.x; y2.y += e2 * xq.y; y2.z += e2 * xq.z; y2.w += e2 * xq.w;
        y3.x += e3 * xq.x; y3.y += e3 * xq.y; y3.z += e3 * xq.z; y3.w += e3 * xq.w;
        zq.x += dis * xq.x; zq.y += dis * xq.y; zq.z += dis * xq.z; zq.w += dis * xq.w;
    }
    // gather full z (14 valid) before any lane can exit
    float zf[16];
#pragma unroll
    for (int q = 0; q < 4; q++) {
        int src = (lane & ~3) | q;
        zf[q * 4 + 0] = __shfl_sync(qmask, zq.x, src);
        zf[q * 4 + 1] = __shfl_sync(qmask, zq.y, src);
        zf[q * 4 + 2] = __shfl_sync(qmask, zq.z, src);
        zf[q * 4 + 3] = __shfl_sync(qmask, zq.w, src);
    }
    if (!valid) return;
    d_den[n * 4 + p] = den;
    // y: head h's quarter p lives in register y[p^h]
#pragma unroll
    for (int h = 0; h < 4; h++) {
        int j = h ^ p;
        float4 v = (j == 0) ? y0 : (j == 1) ? y1 : (j == 2) ? y2 : y3;
        *(float4*)(d_y + (long)n * 64 + h * 16 + p * 4) = v;
    }
    // gc: lane p computes 16 columns [16p, 16p+16)
    float dvn = d_xp[n * 16 + 14];
    int c0 = p * 16;
    float4* gout = (float4*)(d_gc + (long)n * 64 + c0);
#pragma unroll
    for (int c4 = 0; c4 < 4; c4++) {
        float a0 = 0.f, a1 = 0.f, a2 = 0.f, a3 = 0.f;
#pragma unroll
        for (int k = 0; k < 14; k++) {
            float zv = zf[k];
            const float* wr = &sWg[k][c0 + c4 * 4];
            a0 += zv * wr[0]; a1 += zv * wr[1]; a2 += zv * wr[2]; a3 += zv * wr[3];
        }
        gout[c4] = make_float4(fmaxf(dvn * a0 + sbg[c0 + c4 * 4 + 0], 0.f),
                               fmaxf(dvn * a1 + sbg[c0 + c4 * 4 + 1], 0.f),
                               fmaxf(dvn * a2 + sbg[c0 + c4 * 4 + 2], 0.f),
                               fmaxf(dvn * a3 + sbg[c0 + c4 * 4 + 3], 0.f));
    }
}

// ---------------- fuse2: h2 = elu((y/den)@W1 + b1) @ W2, g1 never materialized ----------------
__global__ void k_fuse2(const float* __restrict__ W1, const float* __restrict__ b1,
                        const float* __restrict__ W2,
                        const float* __restrict__ as2, const float* __restrict__ ad2) {
    __shared__ float sA[64][68];
    __shared__ float sB[64][68];
    __shared__ float sW1c[14][64];
    __shared__ float sYc[64][16];
    __shared__ float sden[64];
    __shared__ float sb1c[64];
    int t = threadIdx.x;
    int nb = blockIdx.x * 64;
    int tn = t >> 4, tc = t & 15;
    float acc[4][4] = {};
#pragma unroll 1
    for (int kc = 0; kc < 4; kc++) {
#pragma unroll
        for (int j = 0; j < 4; j++) {
            int f4 = t * 4 + j;
            int row = f4 >> 4, col4 = f4 & 15;
            float4 wv = ((const float4*)(W2 + (kc * 64 + row) * 64))[col4];
            ((float4*)&sB[row][0])[col4] = wv;
        }
        for (int i = t; i < 14 * 64; i += 256) {
            int k = i >> 6, c = i & 63;
            sW1c[k][c] = W1[k * 256 + kc * 64 + c];
        }
        // y rows are [n][h][16]: 16-float chunks, float4 loads
        for (int i = t; i < 64 * 4; i += 256) {
            int row = i >> 2, q = i & 3;
            int n = nb + row;
            float4 v = (n < NN) ? *(const float4*)(d_y + (long)n * 64 + kc * 16 + q * 4)
                                : make_float4(0.f, 0.f, 0.f, 0.f);
            ((float4*)&sYc[row][0])[q] = v;
        }
        if (t < 64) {
            int n = nb + t;
            sden[t] = (n < NN) ? d_den[n * 4 + kc] : 1.f;
            sb1c[t] = b1[kc * 64 + t];
        }
        __syncthreads();
        {
            float invr[4];
#pragma unroll
            for (int i = 0; i < 4; i++) invr[i] = 1.f / (sden[tn * 4 + i] + 1e-16f);
            float accb[4][4] = {};
#pragma unroll
            for (int k = 0; k < 14; k++) {
                float yv0 = sYc[tn * 4 + 0][k], yv1 = sYc[tn * 4 + 1][k];
                float yv2 = sYc[tn * 4 + 2][k], yv3 = sYc[tn * 4 + 3][k];
                float wv0 = sW1c[k][tc * 4 + 0], wv1 = sW1c[k][tc * 4 + 1];
                float wv2 = sW1c[k][tc * 4 + 2], wv3 = sW1c[k][tc * 4 + 3];
                accb[0][0] += yv0 * wv0; accb[0][1] += yv0 * wv1; accb[0][2] += yv0 * wv2; accb[0][3] += yv0 * wv3;
                accb[1][0] += yv1 * wv0; accb[1][1] += yv1 * wv1; accb[1][2] += yv1 * wv2; accb[1][3] += yv1 * wv3;
                accb[2][0] += yv2 * wv0; accb[2][1] += yv2 * wv1; accb[2][2] += yv2 * wv2; accb[2][3] += yv2 * wv3;
                accb[3][0] += yv3 * wv0; accb[3][1] += yv3 * wv1; accb[3][2] += yv3 * wv2; accb[3][3] += yv3 * wv3;
            }
#pragma unroll
            for (int i = 0; i < 4; i++)
#pragma unroll
                for (int j = 0; j < 4; j++)
                    sA[tn * 4 + i][tc * 4 + j] = elu(accb[i][j] * invr[i] + sb1c[tc * 4 + j]);
        }
        __syncthreads();
#pragma unroll 4
        for (int kk = 0; kk < 64; kk++) {
            float4 bv = ((float4*)&sB[kk][0])[tc];
#pragma unroll
            for (int i = 0; i < 4; i++) {
                float av = sA[tn * 4 + i][kk];
                acc[i][0] += av * bv.x; acc[i][1] += av * bv.y;
                acc[i][2] += av * bv.z; acc[i][3] += av * bv.w;
            }
        }
        __syncthreads();
    }
    float4 av2 = ((const float4*)as2)[tc];
    float4 dv2 = ((const float4*)ad2)[tc];
#pragma unroll
    for (int i = 0; i < 4; i++) {
        int n = nb + tn * 4 + i;
        float ps = acc[i][0] * av2.x + acc[i][1] * av2.y + acc[i][2] * av2.z + acc[i][3] * av2.w;
        float pd = acc[i][0] * dv2.x + acc[i][1] * dv2.y + acc[i][2] * dv2.z + acc[i][3] * dv2.w;
#pragma unroll
        for (int o = 8; o > 0; o >>= 1) {
            ps += __shfl_down_sync(0xFFFFFFFFu, ps, o, 16);
            pd += __shfl_down_sync(0xFFFFFFFFu, pd, o, 16);
        }
        if (n < NN) {
            ((float4*)(d_h2 + (long)n * 64))[tc] =
                make_float4(acc[i][0], acc[i][1], acc[i][2], acc[i][3]);
            if (tc == 0) { d_ss2[n] = ps; d_sd2[n] = pd; }
        }
    }
}

// ---------------- gat2lite: warp per node -> g2 = elu(softmax-agg(h2) + b2) ----------------
__global__ void k_gat2lite(const float* __restrict__ b2) {
    __shared__ int spre[SB + 1];
    int t = threadIdx.x, lane = t & 31, w = t >> 5;
    load_spre(spre, t);
    int c = 2 * lane;
    float b2a = __ldg(b2 + c), b2b = __ldg(b2 + c + 1);
    __syncthreads();
    int n = blockIdx.x * 8 + w;
    if (n >= NN) return;
    float sdv = d_sd2[n];
    int beg = d_off[n] + spre[n >> 10];
    int end = d_off[n + 1] + spre[(n + 1) >> 10];
    float a0 = 0.f, a1 = 0.f, den = 0.f;
    int i = beg;
    for (; i + 2 <= end; i += 2) {
        int s0 = d_csr[i], s1 = d_csr[i + 1];
        float l0 = d_ss2[s0], l1 = d_ss2[s1];
        float2 h0 = ((const float2*)(d_h2 + (long)s0 * 64))[lane];
        float2 h1v = ((const float2*)(d_h2 + (long)s1 * 64))[lane];
        float e0 = __expf(lrelu(l0 + sdv));
        float e1 = __expf(lrelu(l1 + sdv));
        den += e0 + e1;
        a0 += h0.x * e0 + h1v.x * e1;
        a1 += h0.y * e0 + h1v.y * e1;
    }
    if (i < end) {
        int s = d_csr[i];
        float e = __expf(lrelu(d_ss2[s] + sdv));
        den += e;
        float2 h = ((const float2*)(d_h2 + (long)s * 64))[lane];
        a0 += h.x * e; a1 += h.y * e;
    }
    float inv = 1.f / (den + 1e-16f);
    ((float2*)(d_g2 + (long)n * 64))[lane] =
        make_float2(elu(a0 * inv + b2a), elu(a1 * inv + b2b));
}

// ---------------- pool: fused = relu([g2|gc]@Wf + bf); segment-reduced pooling + gcnt ----------------
__global__ void k_pool(const float* __restrict__ Wf, const float* __restrict__ bf,
                       const int* __restrict__ batch) {
    __shared__ float sA[64][68];
    __shared__ float sB[64][68];
    __shared__ int sBt[64];
    int t = threadIdx.x;
    int nb = blockIdx.x * 64;
    int tn = t >> 4, tc = t & 15;
    if (t < 64) sBt[t] = (nb + t < NN) ? batch[nb + t] : -1;
    float acc[4][4] = {};
#pragma unroll 1
    for (int kc = 0; kc < 2; kc++) {
        const float* src = kc ? d_gc : d_g2;
#pragma unroll
        for (int j = 0; j < 4; j++) {
            int f4 = t * 4 + j;
            int row = f4 >> 4, col4 = f4 & 15;
            float4 wv = ((const float4*)(Wf + (kc * 64 + row) * 64))[col4];
            ((float4*)&sB[row][0])[col4] = wv;
            int n = nb + row;
            float4 v = (n < NN) ? ((const float4*)(src + (long)n * 64))[col4]
                                : make_float4(0.f, 0.f, 0.f, 0.f);
            ((float4*)&sA[row][0])[col4] = v;
        }
        __syncthreads();
#pragma unroll 4
        for (int kk = 0; kk < 64; kk++) {
            float4 bv = ((float4*)&sB[kk][0])[tc];
#pragma unroll
            for (int i = 0; i < 4; i++) {
                float av = sA[tn * 4 + i][kk];
                acc[i][0] += av * bv.x; acc[i][1] += av * bv.y;
                acc[i][2] += av * bv.z; acc[i][3] += av * bv.w;
            }
        }
        __syncthreads();
    }
    float4 bfv = ((const float4*)bf)[tc];
#pragma unroll
    for (int i = 0; i < 4; i++) {
        int row = tn * 4 + i;
        bool v = (nb + row) < NN;
        sA[row][tc * 4 + 0] = v ? fmaxf(acc[i][0] + bfv.x, 0.f) : 0.f;
        sA[row][tc * 4 + 1] = v ? fmaxf(acc[i][1] + bfv.y, 0.f) : 0.f;
        sA[row][tc * 4 + 2] = v ? fmaxf(acc[i][2] + bfv.z, 0.f) : 0.f;
        sA[row][tc * 4 + 3] = v ? fmaxf(acc[i][3] + bfv.w, 0.f) : 0.f;
    }
    __syncthreads();
    if (t < 64) {
        float run = 0.f;
        int cur = sBt[0];
#pragma unroll 8
        for (int r = 0; r < 64; r++) {
            int b = sBt[r];
            if (b != cur) {
                if (cur >= 0) atomicAdd(d_pooled + cur * 64 + t, run);
                run = 0.f;
                cur = b;
            }
            run += sA[r][t];
        }
        if (cur >= 0) atomicAdd(d_pooled + cur * 64 + t, run);
    } else if (t == 64) {
        int r = 0;
        while (r < 64) {
            int b = sBt[r], r0 = r;
            while (r < 64 && sBt[r] == b) r++;
            if (b >= 0) atomicAdd(&d_gcnt[b], (float)(r - r0));
        }
    }
}

// ---------------- heads: pooled mean -> 2x (relu MLP 64->32->5); self-zero pooled/gcnt ----------------
__global__ void k_head(const float* __restrict__ Wc1, const float* __restrict__ bc1,
                       const float* __restrict__ Wc2, const float* __restrict__ bc2,
                       const float* __restrict__ Wp1, const float* __restrict__ bp1,
                       const float* __restrict__ Wp2, const float* __restrict__ bp2,
                       float* __restrict__ out) {
    int g = blockIdx.x, t = threadIdx.x;
    __shared__ float sp[64], sh[64];
    float cnt = fmaxf(d_gcnt[g], 1.0f);
    sp[t] = d_pooled[g * 64 + t] / cnt;
    d_pooled[g * 64 + t] = 0.f;      // restore for next replay
    if (t == 0) d_gcnt[g] = 0.f;     // restore for next replay
    __syncthreads();
    float hv;
    if (t < 32) {
        hv = bc1[t];
#pragma unroll 8
        for (int k = 0; k < 64; k++) hv += sp[k] * Wc1[k * 32 + t];
    } else {
        int j = t - 32;
        hv = bp1[j];
#pragma unroll 8
        for (int k = 0; k < 64; k++) hv += sp[k] * Wp1[k * 32 + j];
    }
    sh[t] = fmaxf(hv, 0.f);
    __syncthreads();
    if (t < 5) {
        float o = bc2[t];
#pragma unroll
        for (int j = 0; j < 32; j++) o += sh[j] * Wc2[j * 5 + t];
        out[g * 5 + t] = o;
    } else if (t >= 8 && t < 13) {
        int u = t - 8;
        float o = bp2[u];
#pragma unroll
        for (int j = 0; j < 32; j++) o += sh[32 + j] * Wp2[j * 5 + u];
        out[NG * 5 + g * 5 + u] = o;
    }
}

extern "C" void kernel_launch(void* const* d_in, const int* in_sizes, int n_in,
                              void* d_out, int out_size) {
    const float* x     = (const float*)d_in[0];
    const int*   ei    = (const int*)d_in[1];     // int32 (JAX x64 disabled)
    const int*   batch = (const int*)d_in[3];     // int32
    const float* W1  = (const float*)d_in[4];
    const float* as1 = (const float*)d_in[5];
    const float* ad1 = (const float*)d_in[6];
    const float* b1  = (const float*)d_in[7];
    const float* W2  = (const float*)d_in[8];
    const float* as2 = (const float*)d_in[9];
    const float* ad2 = (const float*)d_in[10];
    const float* b2  = (const float*)d_in[11];
    const float* Wg  = (const float*)d_in[12];
    const float* bg  = (const float*)d_in[13];
    const float* Wf  = (const float*)d_in[14];
    const float* bf  = (const float*)d_in[15];
    const float* Wc1 = (const float*)d_in[16];
    const float* bc1 = (const float*)d_in[17];
    const float* Wc2 = (const float*)d_in[18];
    const float* bc2 = (const float*)d_in[19];
    const float* Wp1 = (const float*)d_in[20];
    const float* bp1 = (const float*)d_in[21];
    const float* Wp2 = (const float*)d_in[22];
    const float* bp2 = (const float*)d_in[23];

    int E  = in_sizes[1] / 2;
    int te = E + NN;
    int eb = (te + 255) / 256;

    k_init<<<512, 256>>>(x, W1, as1, ad1, ei, E, te);         // 0
    k_scan1<<<SB, 1024>>>();                                  // 1
    k_fill<<<eb, 256>>>(ei, E, te);                           // 2
    k_gather1<<<(4 * NN + 127) / 128, 128>>>(Wg, bg);         // 3 <- profiled
    k_fuse2<<<(NN + 63) / 64, 256>>>(W1, b1, W2, as2, ad2);   // 4
    k_gat2lite<<<(NN + 7) / 8, 256>>>(b2);                    // 5
    k_pool<<<(NN + 63) / 64, 256>>>(Wf, bf, batch);           // 6
    k_head<<<NG, 64>>>(Wc1, bc1, Wc2, bc2, Wp1, bp1, Wp2, bp2, (float*)d_out); // 7
}